// round 12
// baseline (speedup 1.0000x reference)
#include <cuda_runtime.h>
#include <math.h>

// FLIF fractional LIF — round 12.
// Near/far memory split:
//  - P[12]: lane-LOCAL rotating window, ages 1..12 (uniform weights wrN in
//    regs, every lane redundant). Consume mem_n = P[n%12] -> register read,
//    critical chain has NO shfl: delta -> fma(wr1) -> add -> add -> delta.
//  - M[12]: distributed accumulators for ages 13..384 (lane l owns ages
//    12l+1..12l+12; lanes 1..31 live, lane 0 dead-but-uniform).
//  - Tail for dest n+12 = lane 1's M[n%12] pre-scatter at step n (age-13 term
//    landed at step n-1). Its shfl result is used 12 steps later as the
//    re-init base of the consumed P slot (merged with the age-12 FMA), so the
//    SHFL gets ~12 steps of slack instead of ~1.

#define T_STEPS 384
typedef unsigned long long u64;

__device__ __forceinline__ u64 pack2(float x, float y) {
    u64 r; asm("mov.b64 %0, {%1, %2};" : "=l"(r) : "f"(x), "f"(y)); return r;
}
__device__ __forceinline__ void unpack2(u64 a, float& x, float& y) {
    asm("mov.b64 {%0, %1}, %2;" : "=f"(x), "=f"(y) : "l"(a));
}
__device__ __forceinline__ u64 fma2(u64 a, u64 b, u64 c) {
    u64 d; asm("fma.rn.f32x2 %0, %1, %2, %3;" : "=l"(d) : "l"(a), "l"(b), "l"(c)); return d;
}
__device__ __forceinline__ u64 add2(u64 a, u64 b) {
    u64 d; asm("add.rn.f32x2 %0, %1, %2;" : "=l"(d) : "l"(a), "l"(b)); return d;
}

struct St {
    u64 M[12];      // far negated accumulators (ages 13..384, cyclic)
    u64 P[12];      // near negated window (ages 1..12 + tail base), LOCAL
    u64 wrn[12];    // lane-specific: -wr[12*lane+m+1]  (far scatter weights)
    u64 wrN[12];    // uniform:       -wr[m+1]          (near scatter weights)
    u64 cA, cG, cC; // (-1.75), (-0.025), (COEF) packed
    u64 neg1;       // (-1,-1)
    u64 V2;         // packed previous V
    u64 nr2;        // negated reset for CURRENT step (from previous V)
    bool is0, is31;
    int lnext;
};

// One uniform step for n >= 2.  RR = n % 12 (compile-time).
template<int RR>
__device__ __forceinline__ void step(St& s, const u64* __restrict__ inw,
                                     u64* __restrict__ trcw, int idx)
{
    // cross-lane traffic, both PRE-scatter; results have >=12 steps of slack
    u64 bcT  = __shfl_sync(0xffffffffu, s.M[RR], 1);        // tail for dest n+12
    u64 tmpH = __shfl_sync(0xffffffffu, s.M[RR], s.lnext);  // handoff lane+1 -> lane

    // ---- critical chain (fully local) ----
    u64 a2  = add2(inw[idx], s.cA);           // In - 1.75
    u64 t2  = fma2(s.V2, s.cG, a2);           // -0.025*V + In - 1.75
    u64 u2  = fma2(t2, s.cC, s.V2);           // COEF*(...) + V
    u64 vp2 = add2(u2, s.P[RR]);              // minus memory (local register!)
    u64 vn2 = add2(vp2, s.nr2);               // minus reset
    u64 d2  = fma2(s.V2, s.neg1, vn2);        // delta_n = Vnew - Vprev

    // near scatter: ages 1..11 into future P slots; age 12 merged with the
    // consumed slot's re-init from the tail broadcast (dest n+12)
#pragma unroll
    for (int a = 1; a <= 11; ++a)
        s.P[(RR + a) % 12] = fma2(s.wrN[a - 1], d2, s.P[(RR + a) % 12]);
    s.P[RR] = fma2(s.wrN[11], d2, bcT);

    // far scatter (identical to R5; lane 0's writes are dead but uniform)
    s.M[RR] = s.is31 ? 0ull : tmpH;
#pragma unroll
    for (int j = 0; j < 12; ++j)
        s.M[j] = fma2(s.wrn[(j + 11 - RR) % 12], d2, s.M[j]);

    // off-chain epilogue
    if (s.is0) trcw[idx] = vn2;
    float vnl, vnh; unpack2(vn2, vnl, vnh);
    s.nr2 = pack2((vnl > -50.0f) ? -20.0f : 0.0f,
                  (vnh > -50.0f) ? -20.0f : 0.0f);
    s.V2 = vn2;
}

__global__ __launch_bounds__(32) void flif_kernel(
    const float* __restrict__ I,    // [S, T]
    const float* __restrict__ Wt,   // weights, length Wlen
    float* __restrict__ out,        // [2, S, T]: spikes then trace
    int S, int Wlen, float COEF)
{
    __shared__ u64 in_sh[T_STEPS];
    __shared__ u64 trc_sh[T_STEPS];

    const int lane = threadIdx.x & 31;
    const int pair = blockIdx.x;
    const int sA = pair * 2, sB = sA + 1;

    const float* rowA = I + (size_t)sA * T_STEPS;
    const float* rowB = I + (size_t)sB * T_STEPS;
    for (int t = lane; t < T_STEPS; t += 32)
        in_sh[t] = pack2(rowA[t], rowB[t]);
    __syncwarp();

    St s;
    s.is0 = (lane == 0);
    s.is31 = (lane == 31);
    s.lnext = (lane + 1) & 31;
    s.cA = pack2(-1.75f, -1.75f);
    s.cG = pack2(-0.025f, -0.025f);
    s.cC = pack2(COEF, COEF);
    s.neg1 = pack2(-1.0f, -1.0f);
#pragma unroll
    for (int m = 0; m < 12; ++m) {
        float v = -Wt[Wlen - (12 * lane + m + 1)];   // lane-specific far weights
        s.wrn[m] = pack2(v, v);
        float u = -Wt[Wlen - (m + 1)];               // uniform near weights -wr[m+1]
        s.wrN[m] = pack2(u, u);
    }
#pragma unroll
    for (int j = 0; j < 12; ++j) { s.M[j] = 0ull; s.P[j] = 0ull; }

    // ---- step 0 (exact): V_prev=0 -> spike, Vpre=-70, Vnew=-90; delta_0 NOT scattered
    float V0l = -90.0f, V0h = -90.0f;
    s.V2 = pack2(V0l, V0h);
    if (s.is0) trc_sh[0] = pack2(-90.0f, -90.0f);

    // ---- step 1 (exact): V1 = V + 0.005*(-V + I*40); spike=0 (V0=-90); mem=0
    {
        float ix, iy; unpack2(in_sh[1], ix, iy);
        float vnl = V0l + 0.005f * (-V0l + ix * 40.0f);
        float vnh = V0h + 0.005f * (-V0h + iy * 40.0f);
        u64 d1 = pack2(vnl - V0l, vnh - V0h);
        // near: dests 2..13 (slots (1+a)%12, a=1..12) get -wr[a]*delta_1
#pragma unroll
        for (int a = 1; a <= 12; ++a)
            s.P[(1 + a) % 12] = fma2(s.wrN[a - 1], d1, s.P[(1 + a) % 12]);
        // far: uniform scatter of delta_1 (r = 1 indices)
#pragma unroll
        for (int j = 0; j < 12; ++j)
            s.M[j] = fma2(s.wrn[(j + 10) % 12], d1, s.M[j]);
        s.V2 = pack2(vnl, vnh);
        if (s.is0) trc_sh[1] = pack2(vnl, vnh);
        s.nr2 = pack2((vnl > -50.0f) ? -20.0f : 0.0f,     // reset for step 2
                      (vnh > -50.0f) ? -20.0f : 0.0f);
    }

    // ---- main loop: n = 2 .. 373, 31 iterations of 12 steps
#define BODY12(NB)                              \
    step<2>(s, in_sh, trc_sh, (NB) + 0);        \
    step<3>(s, in_sh, trc_sh, (NB) + 1);        \
    step<4>(s, in_sh, trc_sh, (NB) + 2);        \
    step<5>(s, in_sh, trc_sh, (NB) + 3);        \
    step<6>(s, in_sh, trc_sh, (NB) + 4);        \
    step<7>(s, in_sh, trc_sh, (NB) + 5);        \
    step<8>(s, in_sh, trc_sh, (NB) + 6);        \
    step<9>(s, in_sh, trc_sh, (NB) + 7);        \
    step<10>(s, in_sh, trc_sh, (NB) + 8);       \
    step<11>(s, in_sh, trc_sh, (NB) + 9);       \
    step<0>(s, in_sh, trc_sh, (NB) + 10);       \
    step<1>(s, in_sh, trc_sh, (NB) + 11);

    for (int nb = 2; nb <= T_STEPS - 22; nb += 12) {   // nb = 2,14,...,362
        BODY12(nb)
    }
    // ---- epilogue: n = 374..383
    step<2>(s, in_sh, trc_sh, 374);
    step<3>(s, in_sh, trc_sh, 375);
    step<4>(s, in_sh, trc_sh, 376);
    step<5>(s, in_sh, trc_sh, 377);
    step<6>(s, in_sh, trc_sh, 378);
    step<7>(s, in_sh, trc_sh, 379);
    step<8>(s, in_sh, trc_sh, 380);
    step<9>(s, in_sh, trc_sh, 381);
    step<10>(s, in_sh, trc_sh, 382);
    step<11>(s, in_sh, trc_sh, 383);
#undef BODY12

    __syncwarp();

    // ---- dump: trace directly; spikes derived from trace[t-1]
    const size_t baseA = (size_t)sA * T_STEPS;
    const size_t baseB = (size_t)sB * T_STEPS;
    const size_t off   = (size_t)S * T_STEPS;
    for (int t = lane; t < T_STEPS; t += 32) {
        float vx, vy; unpack2(trc_sh[t], vx, vy);
        out[off + baseA + t] = vx;
        out[off + baseB + t] = vy;
        float sl, sh;
        if (t == 0) { sl = 1.0f; sh = 1.0f; }   // V_prev = 0 > -50
        else {
            float px, py; unpack2(trc_sh[t - 1], px, py);
            sl = (px > -50.0f) ? 1.0f : 0.0f;
            sh = (py > -50.0f) ? 1.0f : 0.0f;
        }
        out[baseA + t] = sl;
        out[baseB + t] = sh;
    }
}

extern "C" void kernel_launch(void* const* d_in, const int* in_sizes, int n_in,
                              void* d_out, int out_size)
{
    const float* I  = (const float*)d_in[0];
    const float* Wt = (const float*)d_in[1];
    float* out = (float*)d_out;

    const int S    = in_sizes[0] / T_STEPS;
    const int Wlen = in_sizes[1];

    const float coef = (float)(pow(0.1, 0.15) * tgamma(2.0 - 0.15) / 0.5);

    const int pairs = S / 2;                 // S = 2048 -> 1024 warp-blocks
    flif_kernel<<<pairs, 32>>>(I, Wt, out, S, Wlen, coef);
}